// round 15
// baseline (speedup 1.0000x reference)
#include <cuda_runtime.h>
#include <cuda_bf16.h>
#include <cstdint>
#include <math.h>

#define NSTEPS 100
#define NU     128
#define BTOT   200000
#define NTHREADS 256
#define NTILES   4
#define CTA_SAMPLES 256

// ---------------- SMEM layout ----------------
// H1[i] (i=0..3) at i*16384 ; H2 ping-pong [b] (b=0,1) at 65536 + b*16384
#define SM_H1   0
#define SM_H2   65536
#define SM_F32  98304

#define F_W3A   0
#define F_W3B   128
#define F_BE0   256      // [2][128]
#define F_BE1   512
#define F_BE2   768
#define F_COEF  1024
#define F_INVAS 1124
#define F_BSQ   1224
#define F_B3    1324     // 2 floats (pad to 1328)
#define F_XS    1328     // float2[4][64] = 512 floats
#define F_PP    1840     // float2[4][4][64] = 2048 floats
#define F_TOTAL 3888
#define SMEM_TOTAL (SM_F32 + F_TOTAL * 4)   // 113856; x2 CTA = 227712 <= 228KB

// ---------------- named barriers (strict alternation, no parity) ----------------
// BH2[i] = 1+i  : WG0 G1(i,k) done       -> WG1 may G2(i,k)
// BH1[i] = 5+i  : WG1 update+halfB done  -> WG0 may halfA+G1(i,k+1)
// BF2[b] = 9+b  : WG1 G2 on H2[b] done   -> WG0 may G1 write H2[b]
// 11 = WG0 internal (128), 12 = WG1 internal (128)
#define BARV_ARRIVE(id) asm volatile("bar.arrive %0, 256;" :: "r"(id))
#define BARV_WAIT(id)   asm volatile("bar.sync %0, 256;"   :: "r"(id) : "memory")
#define BAR_WG0()       asm volatile("bar.sync 11, 128;" ::: "memory")
#define BAR_WG1()       asm volatile("bar.sync 12, 128;" ::: "memory")

// ---------------- helpers ----------------
static __device__ __forceinline__ uint32_t smem_u32(const void* p) {
    uint32_t a;
    asm("{ .reg .u64 t; cvta.to.shared.u64 t, %1; cvt.u32.u64 %0, t; }" : "=r"(a) : "l"(p));
    return a;
}
static __device__ __forceinline__ uint32_t pack_bf16(float lo, float hi) {
    __nv_bfloat162 h = __floats2bfloat162_rn(lo, hi);
    return *reinterpret_cast<uint32_t*>(&h);
}

#define LDSM4(r0, r1, r2, r3, addr)                                              \
    asm volatile("ldmatrix.sync.aligned.m8n8.x4.shared.b16 {%0,%1,%2,%3}, [%4];" \
                 : "=r"(r0), "=r"(r1), "=r"(r2), "=r"(r3) : "r"(addr))

#define STSM4(addr, r0, r1, r2, r3)                                              \
    asm volatile("stmatrix.sync.aligned.m8n8.x4.shared.b16 [%0], {%1,%2,%3,%4};" \
                 :: "r"(addr), "r"(r0), "r"(r1), "r"(r2), "r"(r3) : "memory")

static __device__ __forceinline__ void mma16816(float c[4],
        uint32_t a0, uint32_t a1, uint32_t a2, uint32_t a3,
        uint32_t b0, uint32_t b1) {
    asm volatile(
        "mma.sync.aligned.m16n8k16.row.col.f32.bf16.bf16.f32 "
        "{%0,%1,%2,%3}, {%4,%5,%6,%7}, {%8,%9}, {%0,%1,%2,%3};"
        : "+f"(c[0]), "+f"(c[1]), "+f"(c[2]), "+f"(c[3])
        : "r"(a0), "r"(a1), "r"(a2), "r"(a3), "r"(b0), "r"(b1));
}
static __device__ __forceinline__ void mma16808(float c[4],
        uint32_t a0, uint32_t a1, uint32_t b0) {
    asm volatile(
        "mma.sync.aligned.m16n8k8.row.col.f32.bf16.bf16.f32 "
        "{%0,%1,%2,%3}, {%4,%5}, {%6}, {%0,%1,%2,%3};"
        : "+f"(c[0]), "+f"(c[1]), "+f"(c[2]), "+f"(c[3])
        : "r"(a0), "r"(a1), "r"(b0));
}

// ---- G1: dst = relu(src @ W1 + be1), 64x128x128; stmatrix epilogue ----
static __device__ __forceinline__ void gemm_g1(
    uint32_t srcb, uint32_t dstb, const uint32_t (&B)[4][8][2], const float* be,
    int wg, uint32_t lrowoff, uint32_t r_lo, uint32_t khalf,
    uint32_t ecolq, uint32_t stoffA, uint32_t stoffB)
{
    #pragma unroll 1
    for (int mt = 0; mt < 4; mt++) {
        const uint32_t abase = srcb + (uint32_t)mt * 4096 + lrowoff;

        uint32_t af[8][4];
        #pragma unroll
        for (int kc = 0; kc < 8; kc++)
            LDSM4(af[kc][0], af[kc][1], af[kc][2], af[kc][3],
                  abase + ((((uint32_t)(kc * 2) + khalf) ^ r_lo) << 4));

        float c[4][4];
        #pragma unroll
        for (int nt = 0; nt < 4; nt++)
            #pragma unroll
            for (int q = 0; q < 4; q++) c[nt][q] = 0.f;

        #pragma unroll
        for (int kc = 0; kc < 8; kc++)
            #pragma unroll
            for (int nt = 0; nt < 4; nt++)
                mma16816(c[nt], af[kc][0], af[kc][1], af[kc][2], af[kc][3],
                         B[nt][kc][0], B[nt][kc][1]);

        uint32_t pk[4][2];
        #pragma unroll
        for (int nt = 0; nt < 4; nt++) {
            int col = wg * 32 + nt * 8 + (int)ecolq * 2;
            float bea = be[col], beb = be[col + 1];
            pk[nt][0] = pack_bf16(fmaxf(c[nt][0] + bea, 0.f), fmaxf(c[nt][1] + beb, 0.f));
            pk[nt][1] = pack_bf16(fmaxf(c[nt][2] + bea, 0.f), fmaxf(c[nt][3] + beb, 0.f));
        }
        const uint32_t dst0 = dstb + (uint32_t)mt * 4096;
        STSM4(dst0 + stoffA, pk[0][0], pk[0][1], pk[1][0], pk[1][1]);
        STSM4(dst0 + stoffB, pk[2][0], pk[2][1], pk[3][0], pk[3][1]);
    }
}

// ---- G2 + fused layer3 dot -> fPPt ----
static __device__ __forceinline__ void gemm_g2(
    uint32_t srcb, const uint32_t (&B)[4][8][2], const float* be,
    const float* w3a, const float* w3b, float2* fPPt,
    int wg, uint32_t lrowoff, uint32_t r_lo, uint32_t khalf,
    uint32_t erow, uint32_t ecolq)
{
    #pragma unroll 1
    for (int mt = 0; mt < 4; mt++) {
        const uint32_t abase = srcb + (uint32_t)mt * 4096 + lrowoff;

        uint32_t af[8][4];
        #pragma unroll
        for (int kc = 0; kc < 8; kc++)
            LDSM4(af[kc][0], af[kc][1], af[kc][2], af[kc][3],
                  abase + ((((uint32_t)(kc * 2) + khalf) ^ r_lo) << 4));

        float c[4][4];
        #pragma unroll
        for (int nt = 0; nt < 4; nt++)
            #pragma unroll
            for (int q = 0; q < 4; q++) c[nt][q] = 0.f;

        #pragma unroll
        for (int kc = 0; kc < 8; kc++)
            #pragma unroll
            for (int nt = 0; nt < 4; nt++)
                mma16816(c[nt], af[kc][0], af[kc][1], af[kc][2], af[kc][3],
                         B[nt][kc][0], B[nt][kc][1]);

        float pA0 = 0.f, pA1 = 0.f, pB0 = 0.f, pB1 = 0.f;
        #pragma unroll
        for (int nt = 0; nt < 4; nt++) {
            int col = wg * 32 + nt * 8 + (int)ecolq * 2;
            float bea = be[col], beb = be[col + 1];
            float wa0 = w3a[col], wa1 = w3a[col + 1];
            float wb0 = w3b[col], wb1 = w3b[col + 1];
            float v0 = fmaxf(c[nt][0] + bea, 0.f);
            float v1 = fmaxf(c[nt][1] + beb, 0.f);
            float v2 = fmaxf(c[nt][2] + bea, 0.f);
            float v3 = fmaxf(c[nt][3] + beb, 0.f);
            pA0 = fmaf(v0, wa0, fmaf(v1, wa1, pA0));
            pA1 = fmaf(v0, wb0, fmaf(v1, wb1, pA1));
            pB0 = fmaf(v2, wa0, fmaf(v3, wa1, pB0));
            pB1 = fmaf(v2, wb0, fmaf(v3, wb1, pB1));
        }
        pA0 += __shfl_xor_sync(0xffffffffu, pA0, 1);
        pA1 += __shfl_xor_sync(0xffffffffu, pA1, 1);
        pB0 += __shfl_xor_sync(0xffffffffu, pB0, 1);
        pB1 += __shfl_xor_sync(0xffffffffu, pB1, 1);
        pA0 += __shfl_xor_sync(0xffffffffu, pA0, 2);
        pA1 += __shfl_xor_sync(0xffffffffu, pA1, 2);
        pB0 += __shfl_xor_sync(0xffffffffu, pB0, 2);
        pB1 += __shfl_xor_sync(0xffffffffu, pB1, 2);
        if (ecolq == 0) {
            int r = mt * 16 + (int)erow;
            fPPt[wg * 64 + r]     = make_float2(pA0, pA1);
            fPPt[wg * 64 + r + 8] = make_float2(pB0, pB1);
        }
    }
}

// ---- L0 half: 64 cols (this WG's half), warp covers 16 cols; stmatrix epilogue ----
static __device__ __forceinline__ void layer0_half(
    const float2* xs, uint32_t dstb, const uint32_t (&B0h)[2], const float* be0,
    int cbase, int lane, uint32_t ecolq, uint32_t stoffL)
{
    const bool klane = ((lane & 3) == 0);
    #pragma unroll
    for (int mt = 0; mt < 4; mt++) {
        float c[2][4];
        #pragma unroll
        for (int nt = 0; nt < 2; nt++)
            #pragma unroll
            for (int q = 0; q < 4; q++) c[nt][q] = 0.f;

        int ra = mt * 16 + (lane >> 2);
        uint32_t a0 = 0u, a1 = 0u;
        if (klane) {
            float2 xa = xs[ra];
            float2 xb = xs[ra + 8];
            a0 = pack_bf16(xa.x, xa.y);
            a1 = pack_bf16(xb.x, xb.y);
        }
        mma16808(c[0], a0, a1, B0h[0]);
        mma16808(c[1], a0, a1, B0h[1]);

        uint32_t pk[2][2];
        #pragma unroll
        for (int nt = 0; nt < 2; nt++) {
            int col = cbase + nt * 8 + (int)ecolq * 2;
            float bea = be0[col], beb = be0[col + 1];
            pk[nt][0] = pack_bf16(fmaxf(c[nt][0] + bea, 0.f), fmaxf(c[nt][1] + beb, 0.f));
            pk[nt][1] = pack_bf16(fmaxf(c[nt][2] + bea, 0.f), fmaxf(c[nt][3] + beb, 0.f));
        }
        STSM4(dstb + (uint32_t)mt * 4096 + stoffL,
              pk[0][0], pk[0][1], pk[1][0], pk[1][1]);
    }
}

__global__ void __launch_bounds__(NTHREADS, 2)
ddpm_kernel(const float* __restrict__ noise, const float* __restrict__ z,
            const float* __restrict__ W0, const float* __restrict__ b0,
            const float* __restrict__ W1, const float* __restrict__ b1,
            const float* __restrict__ W2, const float* __restrict__ b2,
            const float* __restrict__ W3, const float* __restrict__ b3,
            const float* __restrict__ E0, const float* __restrict__ E1,
            const float* __restrict__ E2, float* __restrict__ out)
{
    extern __shared__ char smem_raw[];
    const uint32_t sb = smem_u32(smem_raw);
    float* fA = (float*)(smem_raw + SM_F32);
    float2* fXS = (float2*)&fA[F_XS];
    float2* fPP = (float2*)&fA[F_PP];

    const int tid  = threadIdx.x;
    const int lane = tid & 31;
    const int wid  = tid >> 5;
    const bool isWG0 = (wid < 4);
    const int wg   = wid & 3;
    const int cbase = (isWG0 ? 0 : 64) + wg * 16;
    const int base = blockIdx.x * CTA_SAMPLES;

    // ---- prologue ----
    if (tid < 128) {
        fA[F_W3A + tid] = W3[2 * tid];
        fA[F_W3B + tid] = W3[2 * tid + 1];
        fA[F_BE0 + tid] = b0[tid] + E0[99 * NU + tid];
        fA[F_BE1 + tid] = b1[tid] + E1[99 * NU + tid];
        fA[F_BE2 + tid] = b2[tid] + E2[99 * NU + tid];
    }
    {
        int smp = base + tid;       // fXS has 256 entries
        fXS[tid] = (smp < BTOT) ? ((const float2*)noise)[smp] : make_float2(0.f, 0.f);
    }
    if (tid < 2) fA[F_B3 + tid] = b3[tid];
    if (tid == 0) {
        double prod = 1.0;
        for (int t = 0; t < NSTEPS; t++) {
            double xl = -6.0 + 12.0 * (double)t / 99.0;
            double beta = (1.0 / (1.0 + exp(-xl))) * (0.005 - 1e-5) + 1e-5;
            double alpha = 1.0 - beta;
            prod *= alpha;
            fA[F_COEF + t]  = (float)(beta / sqrt(1.0 - prod));
            fA[F_INVAS + t] = (float)(1.0 / sqrt(alpha));
            fA[F_BSQ + t]   = (float)sqrt(beta);
        }
    }

    // ---- weight fragments ----
    uint32_t Bw[4][8][2];
    uint32_t B0h[2] = {0u, 0u};
    {
        const float* Wsrc = isWG0 ? W1 : W2;
        const int n0 = wg * 32 + (lane >> 2);
        const int kb2 = (lane & 3) * 2;
        #pragma unroll
        for (int nt = 0; nt < 4; nt++) {
            int n = n0 + nt * 8;
            #pragma unroll
            for (int kc = 0; kc < 8; kc++) {
                int k0 = kc * 16 + kb2;
                Bw[nt][kc][0] = pack_bf16(Wsrc[k0 * NU + n],       Wsrc[(k0 + 1) * NU + n]);
                Bw[nt][kc][1] = pack_bf16(Wsrc[(k0 + 8) * NU + n], Wsrc[(k0 + 9) * NU + n]);
            }
        }
        if ((lane & 3) == 0) {
            #pragma unroll
            for (int nt = 0; nt < 2; nt++) {
                int n = cbase + nt * 8 + (lane >> 2);
                B0h[nt] = pack_bf16(W0[n], W0[NU + n]);
            }
        }
    }

    // per-lane constants
    const uint32_t r_lo    = (uint32_t)(lane & 7);
    const uint32_t half_l  = (uint32_t)((lane >> 3) & 1);
    const uint32_t khalf   = (uint32_t)(lane >> 4);
    const uint32_t lrowoff = (half_l * 8 + r_lo) * 256;
    const uint32_t erow    = (uint32_t)(lane >> 2);
    const uint32_t ecolq   = (uint32_t)(lane & 3);

    // stmatrix per-lane address offsets
    const uint32_t sm_m   = (uint32_t)(lane >> 3);
    const uint32_t sm_j   = (uint32_t)(lane & 7);
    const uint32_t sm_nt  = sm_m >> 1;
    const uint32_t sm_row = ((sm_m & 1) * 8 + sm_j) * 256;
    const uint32_t stoffA = sm_row + ((((uint32_t)wg * 4 + sm_nt)      ^ sm_j) << 4);
    const uint32_t stoffB = sm_row + ((((uint32_t)wg * 4 + 2 + sm_nt)  ^ sm_j) << 4);
    const uint32_t stoffL = sm_row + ((((uint32_t)(cbase >> 3) + sm_nt) ^ sm_j) << 4);

    __syncthreads();

    // ---- prime: both WGs write their L0 halves for all tiles (step 0) ----
    #pragma unroll 1
    for (int i = 0; i < NTILES; i++)
        layer0_half(&fXS[i * 64], sb + SM_H1 + i * 16384, B0h, &fA[F_BE0],
                    cbase, lane, ecolq, stoffL);
    __syncthreads();

    if (isWG0) {
        // =========== WG0: halfA(k>0) + G1 ===========
        #pragma unroll 1
        for (int k = 0; k < NSTEPS; k++) {
            const int p = k & 1;
            #pragma unroll 1
            for (int i = 0; i < NTILES; i++) {
                if (k > 0) {
                    BARV_WAIT(5 + i);          // BH1[i]
                    layer0_half(&fXS[i * 64], sb + SM_H1 + i * 16384, B0h,
                                &fA[F_BE0 + p * 128], cbase, lane, ecolq, stoffL);
                    BAR_WG0();
                }
                if (k > 0 || i >= 2)
                    BARV_WAIT(9 + (i & 1));    // BF2[b]: H2 buffer free
                gemm_g1(sb + SM_H1 + i * 16384, sb + SM_H2 + (i & 1) * 16384, Bw,
                        &fA[F_BE1 + p * 128], wg, lrowoff, r_lo, khalf,
                        ecolq, stoffA, stoffB);
                BARV_ARRIVE(1 + i);            // BH2[i]
            }
        }
    } else {
        // =========== WG1: G2 + update + halfB ===========
        const int tid2 = tid - 128;
        const int row  = tid2 & 63;

        #pragma unroll 1
        for (int k = 0; k < NSTEPS; k++) {
            const int p  = k & 1;
            const int pn = p ^ 1;
            const int t  = 99 - k;
            const bool last = (k == NSTEPS - 1);

            #pragma unroll 1
            for (int i = 0; i < NTILES; i++) {
                const int smp = base + i * 64 + row;

                float2 zv = make_float2(0.f, 0.f);
                if (tid2 < 64 && smp < BTOT)
                    zv = ((const float2*)z)[(size_t)k * BTOT + smp];
                float be0v = 0.f, be1v = 0.f, be2v = 0.f;
                if (i == 0 && !last) {
                    int tn = t - 1;
                    be0v = b0[tid2] + E0[tn * NU + tid2];
                    be1v = b1[tid2] + E1[tn * NU + tid2];
                    be2v = b2[tid2] + E2[tn * NU + tid2];
                }

                BARV_WAIT(1 + i);              // BH2[i]
                gemm_g2(sb + SM_H2 + (i & 1) * 16384, Bw, &fA[F_BE2 + p * 128],
                        &fA[F_W3A], &fA[F_W3B], &fPP[i * 256], wg,
                        lrowoff, r_lo, khalf, erow, ecolq);
                BARV_ARRIVE(9 + (i & 1));      // BF2[b]: H2 buffer released
                if (i == 0 && !last) {
                    fA[F_BE0 + pn * 128 + tid2] = be0v;
                    fA[F_BE1 + pn * 128 + tid2] = be1v;
                    fA[F_BE2 + pn * 128 + tid2] = be2v;
                }
                BAR_WG1();
                if (tid2 < 64) {
                    float p0 = fA[F_B3], p1 = fA[F_B3 + 1];
                    #pragma unroll
                    for (int g = 0; g < 4; g++) {
                        float2 v = fPP[i * 256 + g * 64 + row];
                        p0 += v.x; p1 += v.y;
                    }
                    float cf = fA[F_COEF + t], ia = fA[F_INVAS + t], bq = fA[F_BSQ + t];
                    float2 xv = fXS[i * 64 + row];
                    float nx0 = (xv.x - cf * p0) * ia + bq * zv.x;
                    float nx1 = (xv.y - cf * p1) * ia + bq * zv.y;
                    if (last) {
                        if (smp < BTOT) ((float2*)out)[smp] = make_float2(nx0, nx1);
                    } else {
                        fXS[i * 64 + row] = make_float2(nx0, nx1);
                    }
                }
                if (!last) {
                    BAR_WG1();                 // fXS + BE visible to all WG1 warps
                    layer0_half(&fXS[i * 64], sb + SM_H1 + i * 16384, B0h,
                                &fA[F_BE0 + pn * 128], cbase, lane, ecolq, stoffL);
                    BARV_ARRIVE(5 + i);        // BH1[i]
                }
            }
        }
    }
}

extern "C" void kernel_launch(void* const* d_in, const int* in_sizes, int n_in,
                              void* d_out, int out_size) {
    (void)in_sizes; (void)n_in; (void)out_size;
    const float* noise = (const float*)d_in[0];
    const float* z     = (const float*)d_in[1];
    const float* W0    = (const float*)d_in[2];
    const float* b0    = (const float*)d_in[3];
    const float* W1    = (const float*)d_in[4];
    const float* b1    = (const float*)d_in[5];
    const float* W2    = (const float*)d_in[6];
    const float* b2    = (const float*)d_in[7];
    const float* W3    = (const float*)d_in[8];
    const float* b3    = (const float*)d_in[9];
    const float* E0    = (const float*)d_in[10];
    const float* E1    = (const float*)d_in[11];
    const float* E2    = (const float*)d_in[12];
    float* out = (float*)d_out;

    cudaFuncSetAttribute(ddpm_kernel, cudaFuncAttributeMaxDynamicSharedMemorySize, SMEM_TOTAL);

    dim3 grid((BTOT + CTA_SAMPLES - 1) / CTA_SAMPLES);
    ddpm_kernel<<<grid, NTHREADS, SMEM_TOTAL>>>(noise, z, W0, b0, W1, b1, W2, b2,
                                                W3, b3, E0, E1, E2, out);
}

// round 16
// speedup vs baseline: 1.0752x; 1.0752x over previous
#include <cuda_runtime.h>
#include <cuda_bf16.h>
#include <cstdint>
#include <math.h>

#define NSTEPS 100
#define NU     128
#define BTOT   200000
#define NTHREADS 256
#define NTILES   3
#define CTA_SAMPLES 192

// ---------------- SMEM layout (R10/R13/R14) ----------------
#define SM_H1   0                    // H1[i] at i*16384 (bf16 64x128, 256B rows)
#define SM_H2   49152                // H2[i] at 49152 + i*16384
#define SM_F32  98304

#define F_W3A   0
#define F_W3B   128
#define F_BE0   256      // [2][128]
#define F_BE1   512
#define F_BE2   768
#define F_COEF  1024
#define F_INVAS 1124
#define F_BSQ   1224
#define F_B3    1324
#define F_XS    1328     // float2[3][64]
#define F_PP    1712     // float2[3][4][64]
#define F_TOTAL 3248
#define SMEM_TOTAL (SM_F32 + F_TOTAL * 4)   // 111296; x2 CTA = 222592

// ---------------- named barriers (strict ping-pong per tile) ----------------
// BH2[i] = 1+i : WG0 G1(i,k) done      -> WG1 may G2(i,k)
// BH1[i] = 4+i : WG1 update+halfB done -> WG0 may halfA+G1(i,k+1)
// 7 = WG0 internal (128), 8 = WG1 internal (128)
#define BARV_ARRIVE(id) asm volatile("bar.arrive %0, 256;" :: "r"(id))
#define BARV_WAIT(id)   asm volatile("bar.sync %0, 256;"   :: "r"(id) : "memory")
#define BAR_WG0()       asm volatile("bar.sync 7, 128;" ::: "memory")
#define BAR_WG1()       asm volatile("bar.sync 8, 128;" ::: "memory")

// ---------------- helpers ----------------
static __device__ __forceinline__ uint32_t smem_u32(const void* p) {
    uint32_t a;
    asm("{ .reg .u64 t; cvta.to.shared.u64 t, %1; cvt.u32.u64 %0, t; }" : "=r"(a) : "l"(p));
    return a;
}
static __device__ __forceinline__ uint32_t pack_bf16(float lo, float hi) {
    __nv_bfloat162 h = __floats2bfloat162_rn(lo, hi);
    return *reinterpret_cast<uint32_t*>(&h);
}

#define LDSM4(r0, r1, r2, r3, addr)                                              \
    asm volatile("ldmatrix.sync.aligned.m8n8.x4.shared.b16 {%0,%1,%2,%3}, [%4];" \
                 : "=r"(r0), "=r"(r1), "=r"(r2), "=r"(r3) : "r"(addr))

#define STSM4(addr, r0, r1, r2, r3)                                              \
    asm volatile("stmatrix.sync.aligned.m8n8.x4.shared.b16 [%0], {%1,%2,%3,%4};" \
                 :: "r"(addr), "r"(r0), "r"(r1), "r"(r2), "r"(r3) : "memory")

static __device__ __forceinline__ void mma16816(float c[4],
        uint32_t a0, uint32_t a1, uint32_t a2, uint32_t a3,
        uint32_t b0, uint32_t b1) {
    asm volatile(
        "mma.sync.aligned.m16n8k16.row.col.f32.bf16.bf16.f32 "
        "{%0,%1,%2,%3}, {%4,%5,%6,%7}, {%8,%9}, {%0,%1,%2,%3};"
        : "+f"(c[0]), "+f"(c[1]), "+f"(c[2]), "+f"(c[3])
        : "r"(a0), "r"(a1), "r"(a2), "r"(a3), "r"(b0), "r"(b1));
}
static __device__ __forceinline__ void mma16808(float c[4],
        uint32_t a0, uint32_t a1, uint32_t b0) {
    asm volatile(
        "mma.sync.aligned.m16n8k8.row.col.f32.bf16.bf16.f32 "
        "{%0,%1,%2,%3}, {%4,%5}, {%6}, {%0,%1,%2,%3};"
        : "+f"(c[0]), "+f"(c[1]), "+f"(c[2]), "+f"(c[3])
        : "r"(a0), "r"(a1), "r"(b0));
}

// ---- G1: dst = relu(src @ W1 + be1), 64x128x128; stmatrix epilogue ----
static __device__ __forceinline__ void gemm_g1(
    uint32_t srcb, uint32_t dstb, const uint32_t (&B)[4][8][2], const float* be,
    int wg, uint32_t lrowoff, uint32_t r_lo, uint32_t khalf,
    uint32_t ecolq, uint32_t stoffA, uint32_t stoffB)
{
    #pragma unroll 1
    for (int mt = 0; mt < 4; mt++) {
        const uint32_t abase = srcb + (uint32_t)mt * 4096 + lrowoff;

        uint32_t af[8][4];
        #pragma unroll
        for (int kc = 0; kc < 8; kc++)
            LDSM4(af[kc][0], af[kc][1], af[kc][2], af[kc][3],
                  abase + ((((uint32_t)(kc * 2) + khalf) ^ r_lo) << 4));

        float c[4][4];
        #pragma unroll
        for (int nt = 0; nt < 4; nt++)
            #pragma unroll
            for (int q = 0; q < 4; q++) c[nt][q] = 0.f;

        #pragma unroll
        for (int kc = 0; kc < 8; kc++)
            #pragma unroll
            for (int nt = 0; nt < 4; nt++)
                mma16816(c[nt], af[kc][0], af[kc][1], af[kc][2], af[kc][3],
                         B[nt][kc][0], B[nt][kc][1]);

        uint32_t pk[4][2];
        #pragma unroll
        for (int nt = 0; nt < 4; nt++) {
            int col = wg * 32 + nt * 8 + (int)ecolq * 2;
            float bea = be[col], beb = be[col + 1];
            pk[nt][0] = pack_bf16(fmaxf(c[nt][0] + bea, 0.f), fmaxf(c[nt][1] + beb, 0.f));
            pk[nt][1] = pack_bf16(fmaxf(c[nt][2] + bea, 0.f), fmaxf(c[nt][3] + beb, 0.f));
        }
        const uint32_t dst0 = dstb + (uint32_t)mt * 4096;
        STSM4(dst0 + stoffA, pk[0][0], pk[0][1], pk[1][0], pk[1][1]);
        STSM4(dst0 + stoffB, pk[2][0], pk[2][1], pk[3][0], pk[3][1]);
    }
}

// ---- G2 + fused layer3 dot -> fPPt ----
static __device__ __forceinline__ void gemm_g2(
    uint32_t srcb, const uint32_t (&B)[4][8][2], const float* be,
    const float* w3a, const float* w3b, float2* fPPt,
    int wg, uint32_t lrowoff, uint32_t r_lo, uint32_t khalf,
    uint32_t erow, uint32_t ecolq)
{
    #pragma unroll 1
    for (int mt = 0; mt < 4; mt++) {
        const uint32_t abase = srcb + (uint32_t)mt * 4096 + lrowoff;

        uint32_t af[8][4];
        #pragma unroll
        for (int kc = 0; kc < 8; kc++)
            LDSM4(af[kc][0], af[kc][1], af[kc][2], af[kc][3],
                  abase + ((((uint32_t)(kc * 2) + khalf) ^ r_lo) << 4));

        float c[4][4];
        #pragma unroll
        for (int nt = 0; nt < 4; nt++)
            #pragma unroll
            for (int q = 0; q < 4; q++) c[nt][q] = 0.f;

        #pragma unroll
        for (int kc = 0; kc < 8; kc++)
            #pragma unroll
            for (int nt = 0; nt < 4; nt++)
                mma16816(c[nt], af[kc][0], af[kc][1], af[kc][2], af[kc][3],
                         B[nt][kc][0], B[nt][kc][1]);

        float pA0 = 0.f, pA1 = 0.f, pB0 = 0.f, pB1 = 0.f;
        #pragma unroll
        for (int nt = 0; nt < 4; nt++) {
            int col = wg * 32 + nt * 8 + (int)ecolq * 2;
            float bea = be[col], beb = be[col + 1];
            float wa0 = w3a[col], wa1 = w3a[col + 1];
            float wb0 = w3b[col], wb1 = w3b[col + 1];
            float v0 = fmaxf(c[nt][0] + bea, 0.f);
            float v1 = fmaxf(c[nt][1] + beb, 0.f);
            float v2 = fmaxf(c[nt][2] + bea, 0.f);
            float v3 = fmaxf(c[nt][3] + beb, 0.f);
            pA0 = fmaf(v0, wa0, fmaf(v1, wa1, pA0));
            pA1 = fmaf(v0, wb0, fmaf(v1, wb1, pA1));
            pB0 = fmaf(v2, wa0, fmaf(v3, wa1, pB0));
            pB1 = fmaf(v2, wb0, fmaf(v3, wb1, pB1));
        }
        pA0 += __shfl_xor_sync(0xffffffffu, pA0, 1);
        pA1 += __shfl_xor_sync(0xffffffffu, pA1, 1);
        pB0 += __shfl_xor_sync(0xffffffffu, pB0, 1);
        pB1 += __shfl_xor_sync(0xffffffffu, pB1, 1);
        pA0 += __shfl_xor_sync(0xffffffffu, pA0, 2);
        pA1 += __shfl_xor_sync(0xffffffffu, pA1, 2);
        pB0 += __shfl_xor_sync(0xffffffffu, pB0, 2);
        pB1 += __shfl_xor_sync(0xffffffffu, pB1, 2);
        if (ecolq == 0) {
            int r = mt * 16 + (int)erow;
            fPPt[wg * 64 + r]     = make_float2(pA0, pA1);
            fPPt[wg * 64 + r + 8] = make_float2(pB0, pB1);
        }
    }
}

// ---- L0 half: 64 cols (this WG's half), warp covers 16 cols; stmatrix epilogue ----
static __device__ __forceinline__ void layer0_half(
    const float2* xs, uint32_t dstb, const uint32_t (&B0h)[2], const float* be0,
    int cbase, int lane, uint32_t ecolq, uint32_t stoffL)
{
    const bool klane = ((lane & 3) == 0);
    #pragma unroll
    for (int mt = 0; mt < 4; mt++) {
        float c[2][4];
        #pragma unroll
        for (int nt = 0; nt < 2; nt++)
            #pragma unroll
            for (int q = 0; q < 4; q++) c[nt][q] = 0.f;

        int ra = mt * 16 + (lane >> 2);
        uint32_t a0 = 0u, a1 = 0u;
        if (klane) {
            float2 xa = xs[ra];
            float2 xb = xs[ra + 8];
            a0 = pack_bf16(xa.x, xa.y);
            a1 = pack_bf16(xb.x, xb.y);
        }
        mma16808(c[0], a0, a1, B0h[0]);
        mma16808(c[1], a0, a1, B0h[1]);

        uint32_t pk[2][2];
        #pragma unroll
        for (int nt = 0; nt < 2; nt++) {
            int col = cbase + nt * 8 + (int)ecolq * 2;
            float bea = be0[col], beb = be0[col + 1];
            pk[nt][0] = pack_bf16(fmaxf(c[nt][0] + bea, 0.f), fmaxf(c[nt][1] + beb, 0.f));
            pk[nt][1] = pack_bf16(fmaxf(c[nt][2] + bea, 0.f), fmaxf(c[nt][3] + beb, 0.f));
        }
        STSM4(dstb + (uint32_t)mt * 4096 + stoffL,
              pk[0][0], pk[0][1], pk[1][0], pk[1][1]);
    }
}

__global__ void __launch_bounds__(NTHREADS, 2)
ddpm_kernel(const float* __restrict__ noise, const float* __restrict__ z,
            const float* __restrict__ W0, const float* __restrict__ b0,
            const float* __restrict__ W1, const float* __restrict__ b1,
            const float* __restrict__ W2, const float* __restrict__ b2,
            const float* __restrict__ W3, const float* __restrict__ b3,
            const float* __restrict__ E0, const float* __restrict__ E1,
            const float* __restrict__ E2, float* __restrict__ out)
{
    extern __shared__ char smem_raw[];
    const uint32_t sb = smem_u32(smem_raw);
    float* fA = (float*)(smem_raw + SM_F32);
    float2* fXS = (float2*)&fA[F_XS];
    float2* fPP = (float2*)&fA[F_PP];
    float* fXSf = (float*)fXS;
    float* fPPf = (float*)fPP;

    const int tid  = threadIdx.x;
    const int lane = tid & 31;
    const int wid  = tid >> 5;
    const bool isWG0 = (wid < 4);
    const int wg   = wid & 3;
    const int cbase = (isWG0 ? 0 : 64) + wg * 16;
    const int base = blockIdx.x * CTA_SAMPLES;

    // ---- prologue ----
    if (tid < 128) {
        fA[F_W3A + tid] = W3[2 * tid];
        fA[F_W3B + tid] = W3[2 * tid + 1];
        fA[F_BE0 + tid] = b0[tid] + E0[99 * NU + tid];
        fA[F_BE1 + tid] = b1[tid] + E1[99 * NU + tid];
        fA[F_BE2 + tid] = b2[tid] + E2[99 * NU + tid];
    }
    if (tid < 192) {
        int smp = base + tid;
        fXS[tid] = (smp < BTOT) ? ((const float2*)noise)[smp] : make_float2(0.f, 0.f);
    }
    if (tid < 2) fA[F_B3 + tid] = b3[tid];
    if (tid == 0) {
        double prod = 1.0;
        for (int t = 0; t < NSTEPS; t++) {
            double xl = -6.0 + 12.0 * (double)t / 99.0;
            double beta = (1.0 / (1.0 + exp(-xl))) * (0.005 - 1e-5) + 1e-5;
            double alpha = 1.0 - beta;
            prod *= alpha;
            fA[F_COEF + t]  = (float)(beta / sqrt(1.0 - prod));
            fA[F_INVAS + t] = (float)(1.0 / sqrt(alpha));
            fA[F_BSQ + t]   = (float)sqrt(beta);
        }
    }

    // ---- weight fragments ----
    uint32_t Bw[4][8][2];
    uint32_t B0h[2] = {0u, 0u};
    {
        const float* Wsrc = isWG0 ? W1 : W2;
        const int n0 = wg * 32 + (lane >> 2);
        const int kb2 = (lane & 3) * 2;
        #pragma unroll
        for (int nt = 0; nt < 4; nt++) {
            int n = n0 + nt * 8;
            #pragma unroll
            for (int kc = 0; kc < 8; kc++) {
                int k0 = kc * 16 + kb2;
                Bw[nt][kc][0] = pack_bf16(Wsrc[k0 * NU + n],       Wsrc[(k0 + 1) * NU + n]);
                Bw[nt][kc][1] = pack_bf16(Wsrc[(k0 + 8) * NU + n], Wsrc[(k0 + 9) * NU + n]);
            }
        }
        if ((lane & 3) == 0) {
            #pragma unroll
            for (int nt = 0; nt < 2; nt++) {
                int n = cbase + nt * 8 + (lane >> 2);
                B0h[nt] = pack_bf16(W0[n], W0[NU + n]);
            }
        }
    }

    // per-lane constants
    const uint32_t r_lo    = (uint32_t)(lane & 7);
    const uint32_t half_l  = (uint32_t)((lane >> 3) & 1);
    const uint32_t khalf   = (uint32_t)(lane >> 4);
    const uint32_t lrowoff = (half_l * 8 + r_lo) * 256;
    const uint32_t erow    = (uint32_t)(lane >> 2);
    const uint32_t ecolq   = (uint32_t)(lane & 3);

    // stmatrix per-lane address offsets
    const uint32_t sm_m   = (uint32_t)(lane >> 3);
    const uint32_t sm_j   = (uint32_t)(lane & 7);
    const uint32_t sm_nt  = sm_m >> 1;
    const uint32_t sm_row = ((sm_m & 1) * 8 + sm_j) * 256;
    const uint32_t stoffA = sm_row + ((((uint32_t)wg * 4 + sm_nt)      ^ sm_j) << 4);
    const uint32_t stoffB = sm_row + ((((uint32_t)wg * 4 + 2 + sm_nt)  ^ sm_j) << 4);
    const uint32_t stoffL = sm_row + ((((uint32_t)(cbase >> 3) + sm_nt) ^ sm_j) << 4);

    __syncthreads();

    // ---- prime: both WGs write their L0 halves for all tiles (step 0) ----
    #pragma unroll 1
    for (int i = 0; i < NTILES; i++)
        layer0_half(&fXS[i * 64], sb + SM_H1 + i * 16384, B0h, &fA[F_BE0],
                    cbase, lane, ecolq, stoffL);
    __syncthreads();

    if (isWG0) {
        // =========== WG0: halfA(k>0) + G1 ===========
        #pragma unroll 1
        for (int k = 0; k < NSTEPS; k++) {
            const int p = k & 1;
            #pragma unroll 1
            for (int i = 0; i < NTILES; i++) {
                if (k > 0) {
                    BARV_WAIT(4 + i);          // BH1[i]
                    layer0_half(&fXS[i * 64], sb + SM_H1 + i * 16384, B0h,
                                &fA[F_BE0 + p * 128], cbase, lane, ecolq, stoffL);
                    BAR_WG0();
                }
                gemm_g1(sb + SM_H1 + i * 16384, sb + SM_H2 + i * 16384, Bw,
                        &fA[F_BE1 + p * 128], wg, lrowoff, r_lo, khalf,
                        ecolq, stoffA, stoffB);
                BARV_ARRIVE(1 + i);            // BH2[i]
            }
        }
    } else {
        // =========== WG1: G2 + update(all 128 threads, comp-split) + halfB ===========
        const int tid2 = tid - 128;
        const int row  = tid2 & 63;
        const int comp = tid2 >> 6;     // 0: x-component, 1: y-component

        #pragma unroll 1
        for (int k = 0; k < NSTEPS; k++) {
            const int p  = k & 1;
            const int pn = p ^ 1;
            const int t  = 99 - k;
            const bool last = (k == NSTEPS - 1);

            #pragma unroll 1
            for (int i = 0; i < NTILES; i++) {
                const int smp = base + i * 64 + row;

                // early global loads
                float zv = 0.f;
                if (smp < BTOT)
                    zv = ((const float*)z)[((size_t)k * BTOT + smp) * 2 + comp];
                float be0v = 0.f, be1v = 0.f, be2v = 0.f;
                if (i == 0 && !last) {
                    int tn = t - 1;
                    be0v = b0[tid2] + E0[tn * NU + tid2];
                    be1v = b1[tid2] + E1[tn * NU + tid2];
                    be2v = b2[tid2] + E2[tn * NU + tid2];
                }

                BARV_WAIT(1 + i);              // BH2[i]
                gemm_g2(sb + SM_H2 + i * 16384, Bw, &fA[F_BE2 + p * 128],
                        &fA[F_W3A], &fA[F_W3B], &fPP[i * 256], wg,
                        lrowoff, r_lo, khalf, erow, ecolq);
                if (i == 0 && !last) {
                    fA[F_BE0 + pn * 128 + tid2] = be0v;
                    fA[F_BE1 + pn * 128 + tid2] = be1v;
                    fA[F_BE2 + pn * 128 + tid2] = be2v;
                }
                BAR_WG1();
                {
                    // per-component x update: thread handles (row, comp)
                    float pacc = fA[F_B3 + comp];
                    #pragma unroll
                    for (int g = 0; g < 4; g++)
                        pacc += fPPf[(i * 256 + g * 64 + row) * 2 + comp];
                    float cf = fA[F_COEF + t], ia = fA[F_INVAS + t], bq = fA[F_BSQ + t];
                    float xv = fXSf[(i * 64 + row) * 2 + comp];
                    float nx = (xv - cf * pacc) * ia + bq * zv;
                    if (last) {
                        if (smp < BTOT) ((float*)out)[smp * 2 + comp] = nx;
                    } else {
                        fXSf[(i * 64 + row) * 2 + comp] = nx;
                    }
                }
                if (!last) {
                    BAR_WG1();                 // fXS + BE visible to all WG1 warps
                    layer0_half(&fXS[i * 64], sb + SM_H1 + i * 16384, B0h,
                                &fA[F_BE0 + pn * 128], cbase, lane, ecolq, stoffL);
                    BARV_ARRIVE(4 + i);        // BH1[i]
                }
            }
        }
    }
}

extern "C" void kernel_launch(void* const* d_in, const int* in_sizes, int n_in,
                              void* d_out, int out_size) {
    (void)in_sizes; (void)n_in; (void)out_size;
    const float* noise = (const float*)d_in[0];
    const float* z     = (const float*)d_in[1];
    const float* W0    = (const float*)d_in[2];
    const float* b0    = (const float*)d_in[3];
    const float* W1    = (const float*)d_in[4];
    const float* b1    = (const float*)d_in[5];
    const float* W2    = (const float*)d_in[6];
    const float* b2    = (const float*)d_in[7];
    const float* W3    = (const float*)d_in[8];
    const float* b3    = (const float*)d_in[9];
    const float* E0    = (const float*)d_in[10];
    const float* E1    = (const float*)d_in[11];
    const float* E2    = (const float*)d_in[12];
    float* out = (float*)d_out;

    cudaFuncSetAttribute(ddpm_kernel, cudaFuncAttributeMaxDynamicSharedMemorySize, SMEM_TOTAL);

    dim3 grid((BTOT + CTA_SAMPLES - 1) / CTA_SAMPLES);
    ddpm_kernel<<<grid, NTHREADS, SMEM_TOTAL>>>(noise, z, W0, b0, W1, b1, W2, b2,
                                                W3, b3, E0, E1, E2, out);
}

// round 17
// speedup vs baseline: 1.0876x; 1.0116x over previous
#include <cuda_runtime.h>
#include <cuda_bf16.h>
#include <cstdint>
#include <math.h>

#define NSTEPS 100
#define NU     128
#define BTOT   200000
#define NTHREADS 256
#define NTILES   3
#define CTA_SAMPLES 192

// ---------------- SMEM layout (R14) ----------------
#define SM_H1   0                    // H1[i] at i*16384 (bf16 64x128, 256B rows)
#define SM_H2   49152                // H2[i] at 49152 + i*16384
#define SM_F32  98304

#define F_W3I   0        // 256 floats: W3 row-major (w3[c][0], w3[c][1], ...)
#define F_BE0   256      // [2][128]
#define F_BE1   512
#define F_BE2   768
#define F_COEF  1024
#define F_INVAS 1124
#define F_BSQ   1224
#define F_B3    1324
#define F_XS    1328     // float2[3][64]
#define F_PP    1712     // float2[3][4][64]
#define F_TOTAL 3248
#define SMEM_TOTAL (SM_F32 + F_TOTAL * 4)   // 111296; x2 CTA = 222592

// ---------------- named barriers (strict ping-pong per tile) ----------------
// BH2[i] = 1+i : WG0 G1(i,k) done      -> WG1 may G2(i,k)
// BH1[i] = 4+i : WG1 update+halfB done -> WG0 may halfA+G1(i,k+1)
// 7 = WG0 internal (128), 8 = WG1 internal (128)
#define BARV_ARRIVE(id) asm volatile("bar.arrive %0, 256;" :: "r"(id))
#define BARV_WAIT(id)   asm volatile("bar.sync %0, 256;"   :: "r"(id) : "memory")
#define BAR_WG0()       asm volatile("bar.sync 7, 128;" ::: "memory")
#define BAR_WG1()       asm volatile("bar.sync 8, 128;" ::: "memory")

// ---------------- helpers ----------------
static __device__ __forceinline__ uint32_t smem_u32(const void* p) {
    uint32_t a;
    asm("{ .reg .u64 t; cvta.to.shared.u64 t, %1; cvt.u32.u64 %0, t; }" : "=r"(a) : "l"(p));
    return a;
}
static __device__ __forceinline__ uint32_t pack_bf16(float lo, float hi) {
    __nv_bfloat162 h = __floats2bfloat162_rn(lo, hi);
    return *reinterpret_cast<uint32_t*>(&h);
}

#define LDSM4(r0, r1, r2, r3, addr)                                              \
    asm volatile("ldmatrix.sync.aligned.m8n8.x4.shared.b16 {%0,%1,%2,%3}, [%4];" \
                 : "=r"(r0), "=r"(r1), "=r"(r2), "=r"(r3) : "r"(addr))

#define STSM4(addr, r0, r1, r2, r3)                                              \
    asm volatile("stmatrix.sync.aligned.m8n8.x4.shared.b16 [%0], {%1,%2,%3,%4};" \
                 :: "r"(addr), "r"(r0), "r"(r1), "r"(r2), "r"(r3) : "memory")

static __device__ __forceinline__ void mma16816(float c[4],
        uint32_t a0, uint32_t a1, uint32_t a2, uint32_t a3,
        uint32_t b0, uint32_t b1) {
    asm volatile(
        "mma.sync.aligned.m16n8k16.row.col.f32.bf16.bf16.f32 "
        "{%0,%1,%2,%3}, {%4,%5,%6,%7}, {%8,%9}, {%0,%1,%2,%3};"
        : "+f"(c[0]), "+f"(c[1]), "+f"(c[2]), "+f"(c[3])
        : "r"(a0), "r"(a1), "r"(a2), "r"(a3), "r"(b0), "r"(b1));
}
static __device__ __forceinline__ void mma16808(float c[4],
        uint32_t a0, uint32_t a1, uint32_t b0) {
    asm volatile(
        "mma.sync.aligned.m16n8k8.row.col.f32.bf16.bf16.f32 "
        "{%0,%1,%2,%3}, {%4,%5}, {%6}, {%0,%1,%2,%3};"
        : "+f"(c[0]), "+f"(c[1]), "+f"(c[2]), "+f"(c[3])
        : "r"(a0), "r"(a1), "r"(b0));
}

// ---- G1: dst = relu(src @ W1 + be1), 64x128x128; stmatrix epilogue,
//      be loads hoisted (mt-invariant, float2) ----
static __device__ __forceinline__ void gemm_g1(
    uint32_t srcb, uint32_t dstb, const uint32_t (&B)[4][8][2], const float* be,
    int wg, uint32_t lrowoff, uint32_t r_lo, uint32_t khalf,
    uint32_t ecolq, uint32_t stoffA, uint32_t stoffB)
{
    float2 bev[4];
    #pragma unroll
    for (int nt = 0; nt < 4; nt++)
        bev[nt] = *(const float2*)&be[wg * 32 + nt * 8 + (int)ecolq * 2];

    #pragma unroll 1
    for (int mt = 0; mt < 4; mt++) {
        const uint32_t abase = srcb + (uint32_t)mt * 4096 + lrowoff;

        uint32_t af[8][4];
        #pragma unroll
        for (int kc = 0; kc < 8; kc++)
            LDSM4(af[kc][0], af[kc][1], af[kc][2], af[kc][3],
                  abase + ((((uint32_t)(kc * 2) + khalf) ^ r_lo) << 4));

        float c[4][4];
        #pragma unroll
        for (int nt = 0; nt < 4; nt++)
            #pragma unroll
            for (int q = 0; q < 4; q++) c[nt][q] = 0.f;

        #pragma unroll
        for (int kc = 0; kc < 8; kc++)
            #pragma unroll
            for (int nt = 0; nt < 4; nt++)
                mma16816(c[nt], af[kc][0], af[kc][1], af[kc][2], af[kc][3],
                         B[nt][kc][0], B[nt][kc][1]);

        uint32_t pk[4][2];
        #pragma unroll
        for (int nt = 0; nt < 4; nt++) {
            pk[nt][0] = pack_bf16(fmaxf(c[nt][0] + bev[nt].x, 0.f),
                                  fmaxf(c[nt][1] + bev[nt].y, 0.f));
            pk[nt][1] = pack_bf16(fmaxf(c[nt][2] + bev[nt].x, 0.f),
                                  fmaxf(c[nt][3] + bev[nt].y, 0.f));
        }
        const uint32_t dst0 = dstb + (uint32_t)mt * 4096;
        STSM4(dst0 + stoffA, pk[0][0], pk[0][1], pk[1][0], pk[1][1]);
        STSM4(dst0 + stoffB, pk[2][0], pk[2][1], pk[3][0], pk[3][1]);
    }
}

// ---- G2 + fused layer3 dot -> fPPt; vectorized be (float2) + w3 (float4) ----
static __device__ __forceinline__ void gemm_g2(
    uint32_t srcb, const uint32_t (&B)[4][8][2], const float* be,
    const float* w3i, float2* fPPt,
    int wg, uint32_t lrowoff, uint32_t r_lo, uint32_t khalf,
    uint32_t erow, uint32_t ecolq)
{
    #pragma unroll 1
    for (int mt = 0; mt < 4; mt++) {
        const uint32_t abase = srcb + (uint32_t)mt * 4096 + lrowoff;

        uint32_t af[8][4];
        #pragma unroll
        for (int kc = 0; kc < 8; kc++)
            LDSM4(af[kc][0], af[kc][1], af[kc][2], af[kc][3],
                  abase + ((((uint32_t)(kc * 2) + khalf) ^ r_lo) << 4));

        float c[4][4];
        #pragma unroll
        for (int nt = 0; nt < 4; nt++)
            #pragma unroll
            for (int q = 0; q < 4; q++) c[nt][q] = 0.f;

        #pragma unroll
        for (int kc = 0; kc < 8; kc++)
            #pragma unroll
            for (int nt = 0; nt < 4; nt++)
                mma16816(c[nt], af[kc][0], af[kc][1], af[kc][2], af[kc][3],
                         B[nt][kc][0], B[nt][kc][1]);

        float pA0 = 0.f, pA1 = 0.f, pB0 = 0.f, pB1 = 0.f;
        #pragma unroll
        for (int nt = 0; nt < 4; nt++) {
            int col = wg * 32 + nt * 8 + (int)ecolq * 2;
            float2 bev = *(const float2*)&be[col];
            float4 w3v = *(const float4*)&w3i[2 * col];   // {wa0, wb0, wa1, wb1}
            float v0 = fmaxf(c[nt][0] + bev.x, 0.f);
            float v1 = fmaxf(c[nt][1] + bev.y, 0.f);
            float v2 = fmaxf(c[nt][2] + bev.x, 0.f);
            float v3 = fmaxf(c[nt][3] + bev.y, 0.f);
            pA0 = fmaf(v0, w3v.x, fmaf(v1, w3v.z, pA0));
            pA1 = fmaf(v0, w3v.y, fmaf(v1, w3v.w, pA1));
            pB0 = fmaf(v2, w3v.x, fmaf(v3, w3v.z, pB0));
            pB1 = fmaf(v2, w3v.y, fmaf(v3, w3v.w, pB1));
        }
        pA0 += __shfl_xor_sync(0xffffffffu, pA0, 1);
        pA1 += __shfl_xor_sync(0xffffffffu, pA1, 1);
        pB0 += __shfl_xor_sync(0xffffffffu, pB0, 1);
        pB1 += __shfl_xor_sync(0xffffffffu, pB1, 1);
        pA0 += __shfl_xor_sync(0xffffffffu, pA0, 2);
        pA1 += __shfl_xor_sync(0xffffffffu, pA1, 2);
        pB0 += __shfl_xor_sync(0xffffffffu, pB0, 2);
        pB1 += __shfl_xor_sync(0xffffffffu, pB1, 2);
        if (ecolq == 0) {
            int r = mt * 16 + (int)erow;
            fPPt[wg * 64 + r]     = make_float2(pA0, pA1);
            fPPt[wg * 64 + r + 8] = make_float2(pB0, pB1);
        }
    }
}

// ---- L0 half: 64 cols, warp covers 16; stmatrix epilogue, hoisted be ----
static __device__ __forceinline__ void layer0_half(
    const float2* xs, uint32_t dstb, const uint32_t (&B0h)[2], const float* be0,
    int cbase, int lane, uint32_t ecolq, uint32_t stoffL)
{
    const bool klane = ((lane & 3) == 0);
    float2 bev[2];
    #pragma unroll
    for (int nt = 0; nt < 2; nt++)
        bev[nt] = *(const float2*)&be0[cbase + nt * 8 + (int)ecolq * 2];

    #pragma unroll
    for (int mt = 0; mt < 4; mt++) {
        float c[2][4];
        #pragma unroll
        for (int nt = 0; nt < 2; nt++)
            #pragma unroll
            for (int q = 0; q < 4; q++) c[nt][q] = 0.f;

        int ra = mt * 16 + (lane >> 2);
        uint32_t a0 = 0u, a1 = 0u;
        if (klane) {
            float2 xa = xs[ra];
            float2 xb = xs[ra + 8];
            a0 = pack_bf16(xa.x, xa.y);
            a1 = pack_bf16(xb.x, xb.y);
        }
        mma16808(c[0], a0, a1, B0h[0]);
        mma16808(c[1], a0, a1, B0h[1]);

        uint32_t pk[2][2];
        #pragma unroll
        for (int nt = 0; nt < 2; nt++) {
            pk[nt][0] = pack_bf16(fmaxf(c[nt][0] + bev[nt].x, 0.f),
                                  fmaxf(c[nt][1] + bev[nt].y, 0.f));
            pk[nt][1] = pack_bf16(fmaxf(c[nt][2] + bev[nt].x, 0.f),
                                  fmaxf(c[nt][3] + bev[nt].y, 0.f));
        }
        STSM4(dstb + (uint32_t)mt * 4096 + stoffL,
              pk[0][0], pk[0][1], pk[1][0], pk[1][1]);
    }
}

__global__ void __launch_bounds__(NTHREADS, 2)
ddpm_kernel(const float* __restrict__ noise, const float* __restrict__ z,
            const float* __restrict__ W0, const float* __restrict__ b0,
            const float* __restrict__ W1, const float* __restrict__ b1,
            const float* __restrict__ W2, const float* __restrict__ b2,
            const float* __restrict__ W3, const float* __restrict__ b3,
            const float* __restrict__ E0, const float* __restrict__ E1,
            const float* __restrict__ E2, float* __restrict__ out)
{
    extern __shared__ char smem_raw[];
    const uint32_t sb = smem_u32(smem_raw);
    float* fA = (float*)(smem_raw + SM_F32);
    float2* fXS = (float2*)&fA[F_XS];
    float2* fPP = (float2*)&fA[F_PP];

    const int tid  = threadIdx.x;
    const int lane = tid & 31;
    const int wid  = tid >> 5;
    const bool isWG0 = (wid < 4);
    const int wg   = wid & 3;
    const int cbase = (isWG0 ? 0 : 64) + wg * 16;
    const int base = blockIdx.x * CTA_SAMPLES;

    // ---- prologue ----
    if (tid < 128) {
        fA[F_W3I + tid]       = W3[tid];          // W3 row-major copy (256 floats)
        fA[F_W3I + 128 + tid] = W3[128 + tid];
        fA[F_BE0 + tid] = b0[tid] + E0[99 * NU + tid];
        fA[F_BE1 + tid] = b1[tid] + E1[99 * NU + tid];
        fA[F_BE2 + tid] = b2[tid] + E2[99 * NU + tid];
    }
    if (tid < 192) {
        int smp = base + tid;
        fXS[tid] = (smp < BTOT) ? ((const float2*)noise)[smp] : make_float2(0.f, 0.f);
    }
    if (tid < 2) fA[F_B3 + tid] = b3[tid];
    if (tid == 0) {
        double prod = 1.0;
        for (int t = 0; t < NSTEPS; t++) {
            double xl = -6.0 + 12.0 * (double)t / 99.0;
            double beta = (1.0 / (1.0 + exp(-xl))) * (0.005 - 1e-5) + 1e-5;
            double alpha = 1.0 - beta;
            prod *= alpha;
            fA[F_COEF + t]  = (float)(beta / sqrt(1.0 - prod));
            fA[F_INVAS + t] = (float)(1.0 / sqrt(alpha));
            fA[F_BSQ + t]   = (float)sqrt(beta);
        }
    }

    // ---- weight fragments ----
    uint32_t Bw[4][8][2];
    uint32_t B0h[2] = {0u, 0u};
    {
        const float* Wsrc = isWG0 ? W1 : W2;
        const int n0 = wg * 32 + (lane >> 2);
        const int kb2 = (lane & 3) * 2;
        #pragma unroll
        for (int nt = 0; nt < 4; nt++) {
            int n = n0 + nt * 8;
            #pragma unroll
            for (int kc = 0; kc < 8; kc++) {
                int k0 = kc * 16 + kb2;
                Bw[nt][kc][0] = pack_bf16(Wsrc[k0 * NU + n],       Wsrc[(k0 + 1) * NU + n]);
                Bw[nt][kc][1] = pack_bf16(Wsrc[(k0 + 8) * NU + n], Wsrc[(k0 + 9) * NU + n]);
            }
        }
        if ((lane & 3) == 0) {
            #pragma unroll
            for (int nt = 0; nt < 2; nt++) {
                int n = cbase + nt * 8 + (lane >> 2);
                B0h[nt] = pack_bf16(W0[n], W0[NU + n]);
            }
        }
    }

    // per-lane constants
    const uint32_t r_lo    = (uint32_t)(lane & 7);
    const uint32_t half_l  = (uint32_t)((lane >> 3) & 1);
    const uint32_t khalf   = (uint32_t)(lane >> 4);
    const uint32_t lrowoff = (half_l * 8 + r_lo) * 256;
    const uint32_t erow    = (uint32_t)(lane >> 2);
    const uint32_t ecolq   = (uint32_t)(lane & 3);

    // stmatrix per-lane address offsets
    const uint32_t sm_m   = (uint32_t)(lane >> 3);
    const uint32_t sm_j   = (uint32_t)(lane & 7);
    const uint32_t sm_nt  = sm_m >> 1;
    const uint32_t sm_row = ((sm_m & 1) * 8 + sm_j) * 256;
    const uint32_t stoffA = sm_row + ((((uint32_t)wg * 4 + sm_nt)      ^ sm_j) << 4);
    const uint32_t stoffB = sm_row + ((((uint32_t)wg * 4 + 2 + sm_nt)  ^ sm_j) << 4);
    const uint32_t stoffL = sm_row + ((((uint32_t)(cbase >> 3) + sm_nt) ^ sm_j) << 4);

    __syncthreads();

    // ---- prime: both WGs write their L0 halves for all tiles (step 0) ----
    #pragma unroll 1
    for (int i = 0; i < NTILES; i++)
        layer0_half(&fXS[i * 64], sb + SM_H1 + i * 16384, B0h, &fA[F_BE0],
                    cbase, lane, ecolq, stoffL);
    __syncthreads();

    if (isWG0) {
        // =========== WG0: halfA(k>0) + G1 ===========
        #pragma unroll 1
        for (int k = 0; k < NSTEPS; k++) {
            const int p = k & 1;
            #pragma unroll 1
            for (int i = 0; i < NTILES; i++) {
                if (k > 0) {
                    BARV_WAIT(4 + i);          // BH1[i]
                    layer0_half(&fXS[i * 64], sb + SM_H1 + i * 16384, B0h,
                                &fA[F_BE0 + p * 128], cbase, lane, ecolq, stoffL);
                    BAR_WG0();
                }
                gemm_g1(sb + SM_H1 + i * 16384, sb + SM_H2 + i * 16384, Bw,
                        &fA[F_BE1 + p * 128], wg, lrowoff, r_lo, khalf,
                        ecolq, stoffA, stoffB);
                BARV_ARRIVE(1 + i);            // BH2[i]
            }
        }
    } else {
        // =========== WG1: G2 + update + halfB ===========
        const int tid2 = tid - 128;
        const int row  = tid2 & 63;

        #pragma unroll 1
        for (int k = 0; k < NSTEPS; k++) {
            const int p  = k & 1;
            const int pn = p ^ 1;
            const int t  = 99 - k;
            const bool last = (k == NSTEPS - 1);

            #pragma unroll 1
            for (int i = 0; i < NTILES; i++) {
                const int smp = base + i * 64 + row;

                float2 zv = make_float2(0.f, 0.f);
                if (tid2 < 64 && smp < BTOT)
                    zv = ((const float2*)z)[(size_t)k * BTOT + smp];
                float be0v = 0.f, be1v = 0.f, be2v = 0.f;
                if (i == 0 && !last) {
                    int tn = t - 1;
                    be0v = b0[tid2] + E0[tn * NU + tid2];
                    be1v = b1[tid2] + E1[tn * NU + tid2];
                    be2v = b2[tid2] + E2[tn * NU + tid2];
                }

                BARV_WAIT(1 + i);              // BH2[i]
                gemm_g2(sb + SM_H2 + i * 16384, Bw, &fA[F_BE2 + p * 128],
                        &fA[F_W3I], &fPP[i * 256], wg,
                        lrowoff, r_lo, khalf, erow, ecolq);
                if (i == 0 && !last) {
                    fA[F_BE0 + pn * 128 + tid2] = be0v;
                    fA[F_BE1 + pn * 128 + tid2] = be1v;
                    fA[F_BE2 + pn * 128 + tid2] = be2v;
                }
                BAR_WG1();
                if (tid2 < 64) {
                    float p0 = fA[F_B3], p1 = fA[F_B3 + 1];
                    #pragma unroll
                    for (int g = 0; g < 4; g++) {
                        float2 v = fPP[i * 256 + g * 64 + row];
                        p0 += v.x; p1 += v.y;
                    }
                    float cf = fA[F_COEF + t], ia = fA[F_INVAS + t], bq = fA[F_BSQ + t];
                    float2 xv = fXS[i * 64 + row];
                    float nx0 = (xv.x - cf * p0) * ia + bq * zv.x;
                    float nx1 = (xv.y - cf * p1) * ia + bq * zv.y;
                    if (last) {
                        if (smp < BTOT) ((float2*)out)[smp] = make_float2(nx0, nx1);
                    } else {
                        fXS[i * 64 + row] = make_float2(nx0, nx1);
                    }
                }
                if (!last) {
                    BAR_WG1();                 // fXS + BE visible to all WG1 warps
                    layer0_half(&fXS[i * 64], sb + SM_H1 + i * 16384, B0h,
                                &fA[F_BE0 + pn * 128], cbase, lane, ecolq, stoffL);
                    BARV_ARRIVE(4 + i);        // BH1[i]
                }
            }
        }
    }
}

extern "C" void kernel_launch(void* const* d_in, const int* in_sizes, int n_in,
                              void* d_out, int out_size) {
    (void)in_sizes; (void)n_in; (void)out_size;
    const float* noise = (const float*)d_in[0];
    const float* z     = (const float*)d_in[1];
    const float* W0    = (const float*)d_in[2];
    const float* b0    = (const float*)d_in[3];
    const float* W1    = (const float*)d_in[4];
    const float* b1    = (const float*)d_in[5];
    const float* W2    = (const float*)d_in[6];
    const float* b2    = (const float*)d_in[7];
    const float* W3    = (const float*)d_in[8];
    const float* b3    = (const float*)d_in[9];
    const float* E0    = (const float*)d_in[10];
    const float* E1    = (const float*)d_in[11];
    const float* E2    = (const float*)d_in[12];
    float* out = (float*)d_out;

    cudaFuncSetAttribute(ddpm_kernel, cudaFuncAttributeMaxDynamicSharedMemorySize, SMEM_TOTAL);

    dim3 grid((BTOT + CTA_SAMPLES - 1) / CTA_SAMPLES);
    ddpm_kernel<<<grid, NTHREADS, SMEM_TOTAL>>>(noise, z, W0, b0, W1, b1, W2, b2,
                                                W3, b3, E0, E1, E2, out);
}